// round 5
// baseline (speedup 1.0000x reference)
#include <cuda_runtime.h>

#define NB   32
#define CC   49
#define HW   81
#define PITCH 84          // padded row floats (mult of 4)
#define Q4   21           // PITCH/4
#define OO   24
#define KK   7
#define DD   49
#define RP   56           // padded row count (conv window + fk dd overreach)
#define GP   56           // gs row pitch (c-dim)

// scratch layout [n][c][o][PITCH] so the o-reduction reads contiguous chunks
__device__ float  g_scr[(size_t)NB * CC * OO * PITCH];   // 12.6 MB
__device__ float  g_pre[(size_t)NB * CC * PITCH];        // 527 KB pre-norm (pitched)
__device__ float2 g_part[CC * NB];                       // per (c,n) partial sums

typedef unsigned long long ull;

__device__ __forceinline__ void ffma2(ull& d, ull a, ull b) {
    asm("fma.rn.f32x2 %0, %1, %2, %0;" : "+l"(d) : "l"(a), "l"(b));
}
__device__ __forceinline__ ull pack2(float x) {
    ull r;
    unsigned u = __float_as_uint(x);
    asm("mov.b64 %0, {%1, %1};" : "=l"(r) : "r"(u));
    return r;
}
__device__ __forceinline__ float hadd2(ull v) {
    float2 f = *(float2*)&v;
    return f.x + f.y;
}

__global__ __launch_bounds__(128, 6) void k_main(const float* __restrict__ x,
                                                 const float* __restrict__ w) {
    const int n = blockIdx.x / OO;
    const int o = blockIdx.x % OO;
    // xa: holds xs during load/conv/fk; after fk's register accumulation it is
    // reused (behind a barrier) as gs[dd][c] (54*GP floats = 12096B <= 18816B).
    __shared__ __align__(16) float xa[RP * PITCH];   // 18816 B
    __shared__ __align__(16) float ms[RP * PITCH];   // 18816 B   (total 36.75KB)
    float* const xs = xa;
    float* const gs = xa;
    const int tid = threadIdx.x;

    // ---- load x[n] (pitch 84); zero pad cols 81-83 and rows 49-55 ----
    const float* xn = x + (size_t)n * CC * HW;
    for (int i = tid; i < CC * HW; i += 128) {
        int c = i / HW, hw = i - c * HW;
        xs[c * PITCH + hw] = xn[i];
    }
    for (int i = tid; i < CC * 3; i += 128) {
        int c = i / 3;
        xs[c * PITCH + HW + (i - c * 3)] = 0.f;
    }
    for (int i = tid; i < 7 * PITCH; i += 128) {
        xs[CC * PITCH + i] = 0.f;
        ms[CC * PITCH + i] = 0.f;
    }
    ull wl2[KK];
#pragma unroll
    for (int k = 0; k < KK; k++) wl2[k] = pack2(w[o * KK + k]);
    __syncthreads();

    // ---- depth conv along d: sliding window in regs, 1 load per output ----
    if (tid < 126) {
        int seg = tid / 42;
        int p = tid - seg * 42;
        int d0 = seg * 17;
        int dlen = (seg == 2) ? 15 : 17;
        ull win[KK];
#pragma unroll
        for (int k = 0; k < KK; k++) {
            int r = d0 - 3 + k;
            win[k] = (r >= 0) ? *(const ull*)(xs + r * PITCH + 2 * p) : 0ull;
        }
        for (int d = d0; d < d0 + dlen; d++) {
            ull acc = 0ull;
#pragma unroll
            for (int k = 0; k < KK; k++) ffma2(acc, wl2[k], win[k]);
            *(ull*)(ms + d * PITCH + 2 * p) = acc;
#pragma unroll
            for (int k = 0; k < KK - 1; k++) win[k] = win[k + 1];
            win[6] = *(const ull*)(xs + (d + 4) * PITCH + 2 * p);  // row <= 52, zeroed
        }
    }
    __syncthreads();

    // ---- softmax over hw per row d: warp per row ----
    const int wid = tid >> 5, lane = tid & 31;
    for (int d = wid; d < DD; d += 4) {
        float* row = ms + d * PITCH;
        float m0 = row[lane];
        float m1 = row[lane + 32];
        float m2 = (lane < 17) ? row[lane + 64] : -1e30f;
        float mx = fmaxf(m0, fmaxf(m1, m2));
#pragma unroll
        for (int s = 16; s; s >>= 1) mx = fmaxf(mx, __shfl_xor_sync(~0u, mx, s));
        float e0 = __expf(m0 - mx);
        float e1 = __expf(m1 - mx);
        float e2 = (lane < 17) ? __expf(m2 - mx) : 0.f;
        float sm = e0 + e1 + e2;
#pragma unroll
        for (int s = 16; s; s >>= 1) sm += __shfl_xor_sync(~0u, sm, s);
        float inv = 1.f / sm;
        row[lane]      = e0 * inv;
        row[lane + 32] = e1 * inv;
        if (lane < 17) row[lane + 64] = e2 * inv;
        if (lane < 3)  row[HW + lane] = 0.f;   // keep pad cols zero
    }
    __syncthreads();

    // ---- fk = X * M^T, 117 tiles of 4c x 6dd, f32x2, split operand loads ----
    ull a[4][6];
    int cg = 0, dg = 0;
    if (tid < 117) {
        cg = tid / 9; dg = tid - cg * 9;
#pragma unroll
        for (int i = 0; i < 4; i++)
#pragma unroll
            for (int j = 0; j < 6; j++) a[i][j] = 0ull;
        const float* xp = xs + cg * PITCH;
        const float* mp = ms + dg * PITCH;
#pragma unroll 3
        for (int p2 = 0; p2 < Q4; p2++) {
            // x rows as LDS.128 (covers 2 column-pairs)
            ulonglong2 X0 = *(const ulonglong2*)(xp);
            ulonglong2 X1 = *(const ulonglong2*)(xp + 13 * PITCH);
            ulonglong2 X2 = *(const ulonglong2*)(xp + 26 * PITCH);
            ulonglong2 X3 = *(const ulonglong2*)(xp + 39 * PITCH);
#pragma unroll
            for (int h = 0; h < 2; h++) {
                ull x0 = h ? X0.y : X0.x;
                ull x1 = h ? X1.y : X1.x;
                ull x2 = h ? X2.y : X2.x;
                ull x3 = h ? X3.y : X3.x;
                // first half of dd operands
                {
                    ull b0 = *(const ull*)(mp + 2 * h);
                    ull b1 = *(const ull*)(mp +  9 * PITCH + 2 * h);
                    ull b2 = *(const ull*)(mp + 18 * PITCH + 2 * h);
                    ffma2(a[0][0], x0, b0); ffma2(a[0][1], x0, b1); ffma2(a[0][2], x0, b2);
                    ffma2(a[1][0], x1, b0); ffma2(a[1][1], x1, b1); ffma2(a[1][2], x1, b2);
                    ffma2(a[2][0], x2, b0); ffma2(a[2][1], x2, b1); ffma2(a[2][2], x2, b2);
                    ffma2(a[3][0], x3, b0); ffma2(a[3][1], x3, b1); ffma2(a[3][2], x3, b2);
                }
                // second half
                {
                    ull b3 = *(const ull*)(mp + 27 * PITCH + 2 * h);
                    ull b4 = *(const ull*)(mp + 36 * PITCH + 2 * h);
                    ull b5 = *(const ull*)(mp + 45 * PITCH + 2 * h);
                    ffma2(a[0][3], x0, b3); ffma2(a[0][4], x0, b4); ffma2(a[0][5], x0, b5);
                    ffma2(a[1][3], x1, b3); ffma2(a[1][4], x1, b4); ffma2(a[1][5], x1, b5);
                    ffma2(a[2][3], x2, b3); ffma2(a[2][4], x2, b4); ffma2(a[2][5], x2, b5);
                    ffma2(a[3][3], x3, b3); ffma2(a[3][4], x3, b4); ffma2(a[3][5], x3, b5);
                }
            }
            xp += 4; mp += 4;
        }
    }
    __syncthreads();           // all xs reads done -> xa becomes gs
    if (tid < 117) {
#pragma unroll
        for (int j = 0; j < 6; j++) {
            int dd = dg + 9 * j;
#pragma unroll
            for (int i = 0; i < 4; i++) {
                float s = hadd2(a[i][j]);
                s = (s >= 0.f) ? s : 0.01f * s;   // leaky (mask>0 => sign preserved)
                gs[dd * GP + cg + 13 * i] = s;
            }
        }
    }
    __syncthreads();

    // ---- contrib[c][hw] = sum_dd gs[dd][c] * ms[dd][hw]; 4c x 12hw, f32x2 ----
    if (tid < 91) {
        int pr = tid / 7, qg = tid - pr * 7;
        int c0 = 4 * pr;
        ull A[4][6];
#pragma unroll
        for (int i = 0; i < 4; i++)
#pragma unroll
            for (int k = 0; k < 6; k++) A[i][k] = 0ull;
        const float* gp = gs + c0;
        const float* mq = ms + qg * 12;
#pragma unroll 7
        for (int dd = 0; dd < DD; dd++) {
            float4 g4 = *(const float4*)(gp);
            ull p0 = pack2(g4.x), p1 = pack2(g4.y), p2 = pack2(g4.z), p3 = pack2(g4.w);
            {
                ulonglong2 v0 = *(const ulonglong2*)(mq);
                ffma2(A[0][0], p0, v0.x); ffma2(A[0][1], p0, v0.y);
                ffma2(A[1][0], p1, v0.x); ffma2(A[1][1], p1, v0.y);
                ffma2(A[2][0], p2, v0.x); ffma2(A[2][1], p2, v0.y);
                ffma2(A[3][0], p3, v0.x); ffma2(A[3][1], p3, v0.y);
            }
            {
                ulonglong2 v1 = *(const ulonglong2*)(mq + 4);
                ffma2(A[0][2], p0, v1.x); ffma2(A[0][3], p0, v1.y);
                ffma2(A[1][2], p1, v1.x); ffma2(A[1][3], p1, v1.y);
                ffma2(A[2][2], p2, v1.x); ffma2(A[2][3], p2, v1.y);
                ffma2(A[3][2], p3, v1.x); ffma2(A[3][3], p3, v1.y);
            }
            {
                ulonglong2 v2 = *(const ulonglong2*)(mq + 8);
                ffma2(A[0][4], p0, v2.x); ffma2(A[0][5], p0, v2.y);
                ffma2(A[1][4], p1, v2.x); ffma2(A[1][5], p1, v2.y);
                ffma2(A[2][4], p2, v2.x); ffma2(A[2][5], p2, v2.y);
                ffma2(A[3][4], p3, v2.x); ffma2(A[3][5], p3, v2.y);
            }
            gp += GP; mq += PITCH;
        }
#pragma unroll
        for (int i = 0; i < 4; i++) {
            int c = c0 + i;
            if (c < CC) {
                float* dst = g_scr + ((size_t)(n * CC + c) * OO + o) * PITCH + qg * 12;
                ulonglong2 w0 = {A[i][0], A[i][1]};
                ulonglong2 w1 = {A[i][2], A[i][3]};
                ulonglong2 w2 = {A[i][4], A[i][5]};
                *(ulonglong2*)(dst)     = w0;
                *(ulonglong2*)(dst + 4) = w1;
                *(ulonglong2*)(dst + 8) = w2;
            }
        }
    }
}

// per-(n,c): residual + sum over o (float4, 24-deep MLP), partial stats
__global__ __launch_bounds__(32) void k_sum(const float* __restrict__ x) {
    const int nc = blockIdx.x;              // n*CC + c
    const int q = threadIdx.x;              // 0..31, 21 active float4 columns
    float4 v = {0.f, 0.f, 0.f, 0.f};
    if (q < Q4) {
        const float4* base = (const float4*)g_scr + ((size_t)nc * OO) * Q4 + q;
#pragma unroll
        for (int o = 0; o < OO; o++) {
            float4 t = base[o * Q4];
            v.x += t.x; v.y += t.y; v.z += t.z; v.w += t.w;
        }
        const float* xr = x + (size_t)nc * HW + 4 * q;
        int rem = HW - 4 * q;
        if (rem > 0) v.x += xr[0];
        if (rem > 1) v.y += xr[1];
        if (rem > 2) v.z += xr[2];
        if (rem > 3) v.w += xr[3];
        ((float4*)g_pre)[(size_t)nc * Q4 + q] = v;
    }
    float s  = v.x + v.y + v.z + v.w;
    float s2 = v.x * v.x + v.y * v.y + v.z * v.z + v.w * v.w;
#pragma unroll
    for (int sh = 16; sh; sh >>= 1) {
        s  += __shfl_xor_sync(~0u, s,  sh);
        s2 += __shfl_xor_sync(~0u, s2, sh);
    }
    if (q == 0) {
        int n = nc / CC, c = nc - n * CC;
        g_part[c * NB + n] = make_float2(s, s2);
    }
}

// block per channel: reduce partials -> scale/shift, then normalize
__global__ __launch_bounds__(256) void k_norm(const float* __restrict__ gamma,
                                              const float* __restrict__ beta,
                                              float* __restrict__ out) {
    const int c = blockIdx.x;
    const int tid = threadIdx.x;
    __shared__ float2 ss;
    if (tid < 32) {
        float2 p = g_part[c * NB + tid];
        float s = p.x, s2 = p.y;
#pragma unroll
        for (int sh = 16; sh; sh >>= 1) {
            s  += __shfl_xor_sync(~0u, s,  sh);
            s2 += __shfl_xor_sync(~0u, s2, sh);
        }
        if (tid == 0) {
            const float invM = 1.f / (NB * HW);
            float mean = s * invM;
            float var  = s2 * invM - mean * mean;
            float sc = gamma[c] * rsqrtf(var + 1e-5f);
            ss = make_float2(sc, beta[c] - mean * sc);
        }
    }
    __syncthreads();
    float2 f = ss;
    for (int i = tid; i < NB * HW; i += 256) {
        int n = i / HW, hw = i - n * HW;
        float v = g_pre[(size_t)(n * CC + c) * PITCH + hw];
        out[(size_t)(n * CC + c) * HW + hw] = v * f.x + f.y;
    }
}

extern "C" void kernel_launch(void* const* d_in, const int* in_sizes, int n_in,
                              void* d_out, int out_size) {
    const float* x     = (const float*)d_in[0];
    const float* w     = (const float*)d_in[1];
    // d_in[2] = conv_b: unused (constant per softmax row, cancels)
    const float* gamma = (const float*)d_in[3];
    const float* beta  = (const float*)d_in[4];
    float* out = (float*)d_out;

    k_main<<<NB * OO, 128>>>(x, w);
    k_sum<<<NB * CC, 32>>>(x);
    k_norm<<<CC, 256>>>(gamma, beta, out);
}